// round 7
// baseline (speedup 1.0000x reference)
#include <cuda_runtime.h>
#include <math.h>

#define BATCH 2048
#define NIN   512
#define NOUT  512
#define NB    8
#define NF    52
#define KPACK (NF*NIN)           /* 26624 */
#define PLANE (BATCH*NIN)        /* 1048576 */
#define WPLANE (NIN*NIN)

// ---------------- static device scratch ----------------
__device__ float g_Xt[(size_t)NB*PLANE];    // x blade-major: [i][b][n]
__device__ float g_Wr[(size_t)NB*WPLANE];   // w_right expanded: [i][m][n]
__device__ float g_XR[(size_t)NB*PLANE];    // xr blade-major: [i][b][n]
__device__ float g_U [(size_t)BATCH*KPACK]; // features: [b][f*512+n]
__device__ float g_V [(size_t)NOUT*KPACK];  // packed weights: [m][f*512+n]
__device__ float g_O [(size_t)NB*PLANE];    // output planes: [j][b][m]

// ---------------- f32x2 helpers ----------------
__device__ __forceinline__ unsigned long long ffma2(unsigned long long a,
                                                    unsigned long long b,
                                                    unsigned long long c) {
    unsigned long long d;
    asm("fma.rn.f32x2 %0, %1, %2, %3;" : "=l"(d) : "l"(a), "l"(b), "l"(c));
    return d;
}
__device__ __forceinline__ unsigned long long pack2(float x) {
    unsigned long long d;
    asm("mov.b64 %0, {%1, %2};" : "=l"(d) : "f"(x), "f"(x));
    return d;
}
__device__ __forceinline__ void unpack2(unsigned long long v, float& lo, float& hi) {
    asm("mov.b64 {%0, %1}, %2;" : "=f"(lo), "=f"(hi) : "l"(v));
}

// ---------------- prep kernels ----------------
__global__ void k_transpose_x(const float* __restrict__ x) {
    int n = blockIdx.x * 256 + threadIdx.x;
    int b = blockIdx.y;
    const float4* xp = (const float4*)(x + ((size_t)b*NIN + n)*NB);
    float4 x0 = xp[0], x1 = xp[1];
    size_t o = (size_t)b*NIN + n;
    g_Xt[(size_t)0*PLANE + o] = x0.x;
    g_Xt[(size_t)1*PLANE + o] = x0.y;
    g_Xt[(size_t)2*PLANE + o] = x0.z;
    g_Xt[(size_t)3*PLANE + o] = x0.w;
    g_Xt[(size_t)4*PLANE + o] = x1.x;
    g_Xt[(size_t)5*PLANE + o] = x1.y;
    g_Xt[(size_t)6*PLANE + o] = x1.z;
    g_Xt[(size_t)7*PLANE + o] = x1.w;
}

__global__ void k_expand_w(const float* __restrict__ w_right) {
    int n = blockIdx.x * 256 + threadIdx.x;
    int m = blockIdx.y;
    float4 w = *(const float4*)(w_right + ((size_t)m*NIN + n)*4);
    size_t o = (size_t)m*NIN + n;
    g_Wr[(size_t)0*WPLANE + o] = w.x;
    g_Wr[(size_t)1*WPLANE + o] = w.y;
    g_Wr[(size_t)2*WPLANE + o] = w.y;
    g_Wr[(size_t)3*WPLANE + o] = w.y;
    g_Wr[(size_t)4*WPLANE + o] = w.z;
    g_Wr[(size_t)5*WPLANE + o] = w.z;
    g_Wr[(size_t)6*WPLANE + o] = w.z;
    g_Wr[(size_t)7*WPLANE + o] = w.w;
}

__global__ void k_pack_v(const float* __restrict__ weight, const float* __restrict__ w_left) {
    int n = blockIdx.x * 256 + threadIdx.x;
    int m = blockIdx.y;
    const float* wp = weight + ((size_t)m*NIN + n)*20;
    float w[20];
    #pragma unroll
    for (int q = 0; q < 5; q++) {
        float4 v = *(const float4*)(wp + q*4);
        w[q*4+0] = v.x; w[q*4+1] = v.y; w[q*4+2] = v.z; w[q*4+3] = v.w;
    }
    float4 wl4 = *(const float4*)(w_left + ((size_t)m*NIN + n)*4);
    float wl[4] = {wl4.x, wl4.y, wl4.z, wl4.w};
    const int VMAP[NF] = {
        100, 0, 4, 10, 16,
        101, 1, 5, 6, 11, 12, 17,
        101, 1, 5, 6, 11, 12, 17,
        101, 1, 5, 6, 11, 12, 17,
        102, 2, 7, 8, 13, 14, 18,
        102, 2, 7, 8, 13, 14, 18,
        102, 2, 7, 8, 13, 14, 18,
        103, 3, 9, 15, 19
    };
    float* vb = g_V + (size_t)m*KPACK + n;
    #pragma unroll
    for (int f = 0; f < NF; f++) {
        int c = VMAP[f];
        vb[(size_t)f*NIN] = (c >= 100) ? wl[c - 100] : w[c];
    }
}

// ---------------- normalize xr + build feature matrix U ----------------
__global__ void k_features(const float* __restrict__ x, const float* __restrict__ norm_a) {
    int n = blockIdx.x * 256 + threadIdx.x;
    int b = blockIdx.y;
    const float4* xp = (const float4*)(x + ((size_t)b*NIN + n)*NB);
    float4 x0 = xp[0], x1 = xp[1];
    float X[8] = {x0.x, x0.y, x0.z, x0.w, x1.x, x1.y, x1.z, x1.w};

    size_t o = (size_t)b*NIN + n;
    float R[8];
    #pragma unroll
    for (int i = 0; i < 8; i++) R[i] = g_XR[(size_t)i*PLANE + o];

    float4 na4 = *(const float4*)(norm_a + (size_t)n*4);
    float na[4] = {na4.x, na4.y, na4.z, na4.w};
    float nrm[4];
    nrm[0] = fabsf(R[0]);
    nrm[1] = sqrtf(R[1]*R[1] + R[2]*R[2] + R[3]*R[3]);
    nrm[2] = sqrtf(R[4]*R[4] + R[5]*R[5] + R[6]*R[6]);
    nrm[3] = fabsf(R[7]);
    float inv[4];
    #pragma unroll
    for (int g = 0; g < 4; g++) {
        float sig = 1.0f / (1.0f + __expf(-na[g]));
        float fac = sig * (nrm[g] - 1.0f) + 1.0f + 1e-6f;
        inv[g] = 1.0f / fac;
    }
    R[0] *= inv[0];
    R[1] *= inv[1]; R[2] *= inv[1]; R[3] *= inv[1];
    R[4] *= inv[2]; R[5] *= inv[2]; R[6] *= inv[2];
    R[7] *= inv[3];

    float* Up = g_U + (size_t)b*KPACK + n;
    // blade 0 (scalar)
    Up[(size_t)0*NIN]  = X[0];
    Up[(size_t)1*NIN]  = X[0]*R[0];
    Up[(size_t)2*NIN]  = X[1]*R[1] + X[2]*R[2] + X[3]*R[3];
    Up[(size_t)3*NIN]  = -(X[4]*R[4] + X[5]*R[5] + X[6]*R[6]);
    Up[(size_t)4*NIN]  = -X[7]*R[7];
    // blade 1 (e1)
    Up[(size_t)5*NIN]  = X[1];
    Up[(size_t)6*NIN]  = X[0]*R[1];
    Up[(size_t)7*NIN]  = X[1]*R[0];
    Up[(size_t)8*NIN]  = -X[2]*R[4] - X[3]*R[5];
    Up[(size_t)9*NIN]  = X[4]*R[2] + X[5]*R[3];
    Up[(size_t)10*NIN] = -X[6]*R[7];
    Up[(size_t)11*NIN] = -X[7]*R[6];
    // blade 2 (e2)
    Up[(size_t)12*NIN] = X[2];
    Up[(size_t)13*NIN] = X[0]*R[2];
    Up[(size_t)14*NIN] = X[2]*R[0];
    Up[(size_t)15*NIN] = X[1]*R[4] - X[3]*R[6];
    Up[(size_t)16*NIN] = -X[4]*R[1] + X[6]*R[3];
    Up[(size_t)17*NIN] = X[5]*R[7];
    Up[(size_t)18*NIN] = X[7]*R[5];
    // blade 3 (e3)
    Up[(size_t)19*NIN] = X[3];
    Up[(size_t)20*NIN] = X[0]*R[3];
    Up[(size_t)21*NIN] = X[3]*R[0];
    Up[(size_t)22*NIN] = X[1]*R[5] + X[2]*R[6];
    Up[(size_t)23*NIN] = -X[5]*R[1] - X[6]*R[2];
    Up[(size_t)24*NIN] = -X[4]*R[7];
    Up[(size_t)25*NIN] = -X[7]*R[4];
    // blade 4 (e12)
    Up[(size_t)26*NIN] = X[4];
    Up[(size_t)27*NIN] = X[0]*R[4];
    Up[(size_t)28*NIN] = X[1]*R[2] - X[2]*R[1];
    Up[(size_t)29*NIN] = X[3]*R[7];
    Up[(size_t)30*NIN] = X[4]*R[0];
    Up[(size_t)31*NIN] = -X[5]*R[6] + X[6]*R[5];
    Up[(size_t)32*NIN] = X[7]*R[3];
    // blade 5 (e13)
    Up[(size_t)33*NIN] = X[5];
    Up[(size_t)34*NIN] = X[0]*R[5];
    Up[(size_t)35*NIN] = X[1]*R[3] - X[3]*R[1];
    Up[(size_t)36*NIN] = -X[2]*R[7];
    Up[(size_t)37*NIN] = X[5]*R[0];
    Up[(size_t)38*NIN] = X[4]*R[6] - X[6]*R[4];
    Up[(size_t)39*NIN] = -X[7]*R[2];
    // blade 6 (e23)
    Up[(size_t)40*NIN] = X[6];
    Up[(size_t)41*NIN] = X[0]*R[6];
    Up[(size_t)42*NIN] = X[2]*R[3] - X[3]*R[2];
    Up[(size_t)43*NIN] = X[1]*R[7];
    Up[(size_t)44*NIN] = X[6]*R[0];
    Up[(size_t)45*NIN] = -X[4]*R[5] + X[5]*R[4];
    Up[(size_t)46*NIN] = X[7]*R[1];
    // blade 7 (e123)
    Up[(size_t)47*NIN] = X[7];
    Up[(size_t)48*NIN] = X[0]*R[7];
    Up[(size_t)49*NIN] = X[1]*R[6] - X[2]*R[5] + X[3]*R[4];
    Up[(size_t)50*NIN] = X[4]*R[3] - X[5]*R[2] + X[6]*R[1];
    Up[(size_t)51*NIN] = X[7]*R[0];
}

// ---------------- SGEMM: C(2048x512) = A(2048xK) * B(512xK)^T ----------------
// MODE 0: per-blade xr GEMM (A=g_Xt plane, B=g_Wr plane, C=g_XR plane, K=512)
// MODE 1: per-output-blade feature GEMM (A=g_U slice, B=g_V slice, C=g_O plane)
#define KT 8
#define AS_STRIDE 258
#define BS_STRIDE 130

#define STS_TILE(bufi) do {                                   \
    As[bufi][kq*4+0][rowA]     = a0.x;                        \
    As[bufi][kq*4+1][rowA]     = a0.y;                        \
    As[bufi][kq*4+2][rowA]     = a0.z;                        \
    As[bufi][kq*4+3][rowA]     = a0.w;                        \
    As[bufi][kq*4+0][rowA+128] = a1.x;                        \
    As[bufi][kq*4+1][rowA+128] = a1.y;                        \
    As[bufi][kq*4+2][rowA+128] = a1.z;                        \
    As[bufi][kq*4+3][rowA+128] = a1.w;                        \
    Bs[bufi][kq*4+0][rowA]     = b0.x;                        \
    Bs[bufi][kq*4+1][rowA]     = b0.y;                        \
    Bs[bufi][kq*4+2][rowA]     = b0.z;                        \
    Bs[bufi][kq*4+3][rowA]     = b0.w;                        \
} while (0)

template<int MODE>
__global__ __launch_bounds__(256, 1) void gemm_kernel(
    const float* __restrict__ Abase,
    const float* __restrict__ Bbase,
    float*       __restrict__ Cbase)
{
    __shared__ __align__(16) float As[2][KT][AS_STRIDE];
    __shared__ __align__(16) float Bs[2][KT][BS_STRIDE];

    int z = blockIdx.z;
    const float* A; const float* Bm; float* C;
    size_t lda, ldb; int K;
    if (MODE == 0) {
        A   = Abase + (size_t)z*PLANE;  lda = NIN;
        Bm  = Bbase + (size_t)z*WPLANE; ldb = NIN;
        C   = Cbase + (size_t)z*PLANE;
        K   = NIN;
    } else {
        int F   = (z == 0 || z == 7) ? 5 : 7;
        int off = (z == 0) ? 0 : (5 + 7*(z-1));
        A   = Abase + (size_t)off*NIN;  lda = KPACK;
        Bm  = Bbase + (size_t)off*NIN;  ldb = KPACK;
        C   = Cbase + (size_t)z*PLANE;
        K   = F*NIN;
    }

    int tid = threadIdx.x;
    int tx = tid & 15, ty = tid >> 4;
    int mBlock = blockIdx.x * 256;
    int nBlock = blockIdx.y * 128;

    int rowA = tid >> 1, kq = tid & 1;
    const float* Aptr  = A  + (size_t)(mBlock + rowA) * lda + kq*4;
    const float* Aptr2 = Aptr + (size_t)128 * lda;
    const float* Bptr  = Bm + (size_t)(nBlock + rowA) * ldb + kq*4;

    unsigned long long acc[8][8];
    #pragma unroll
    for (int i = 0; i < 8; i++)
        #pragma unroll
        for (int j = 0; j < 8; j++) acc[i][j] = 0ULL;

    float4 a0 = *(const float4*)Aptr;
    float4 a1 = *(const float4*)Aptr2;
    float4 b0 = *(const float4*)Bptr;
    STS_TILE(0);
    __syncthreads();

    int ntiles = K / KT;
    int buf = 0;
    for (int t = 0; t < ntiles; ++t) {
        if (t + 1 < ntiles) {
            a0 = *(const float4*)(Aptr  + (size_t)(t+1)*KT);
            a1 = *(const float4*)(Aptr2 + (size_t)(t+1)*KT);
            b0 = *(const float4*)(Bptr  + (size_t)(t+1)*KT);
        }
        #pragma unroll
        for (int k = 0; k < KT; ++k) {
            unsigned long long af[8], bb[8];
            #pragma unroll
            for (int i = 0; i < 8; i++)
                af[i] = *(const unsigned long long*)&As[buf][k][2*(ty + 16*i)];
            #pragma unroll
            for (int j = 0; j < 8; j++)
                bb[j] = pack2(Bs[buf][k][tx + 16*j]);
            #pragma unroll
            for (int i = 0; i < 8; i++)
                #pragma unroll
                for (int j = 0; j < 8; j++)
                    acc[i][j] = ffma2(af[i], bb[j], acc[i][j]);
        }
        if (t + 1 < ntiles) { buf ^= 1; STS_TILE(buf); }
        __syncthreads();
    }

    // epilogue: C row-major 2048x512
    #pragma unroll
    for (int i = 0; i < 8; i++) {
        int m = mBlock + 2*(ty + 16*i);
        float* C0 = C + (size_t)m*NOUT + nBlock + tx;
        float* C1 = C0 + NOUT;
        #pragma unroll
        for (int j = 0; j < 8; j++) {
            float lo, hi;
            unpack2(acc[i][j], lo, hi);
            C0[16*j] = lo;
            C1[16*j] = hi;
        }
    }
}

// ---------------- final interleave + bias + 1/sqrt(2) ----------------
__global__ void k_interleave(float* __restrict__ out, const float* __restrict__ b_left) {
    size_t idx = (size_t)blockIdx.x * 256 + threadIdx.x;  // = b*512 + m
    const float r = 0.7071067811865476f;
    int m = (int)(idx & 511);
    float4 o0, o1;
    o0.x = (g_O[(size_t)0*PLANE + idx] + b_left[m]) * r;
    o0.y =  g_O[(size_t)1*PLANE + idx] * r;
    o0.z =  g_O[(size_t)2*PLANE + idx] * r;
    o0.w =  g_O[(size_t)3*PLANE + idx] * r;
    o1.x =  g_O[(size_t)4*PLANE + idx] * r;
    o1.y =  g_O[(size_t)5*PLANE + idx] * r;
    o1.z =  g_O[(size_t)6*PLANE + idx] * r;
    o1.w =  g_O[(size_t)7*PLANE + idx] * r;
    ((float4*)out)[idx*2 + 0] = o0;
    ((float4*)out)[idx*2 + 1] = o1;
}

// ---------------- launch ----------------
extern "C" void kernel_launch(void* const* d_in, const int* in_sizes, int n_in,
                              void* d_out, int out_size) {
    const float* x       = (const float*)d_in[0];
    const float* weight  = (const float*)d_in[1];
    const float* w_right = (const float*)d_in[2];
    const float* w_left  = (const float*)d_in[3];
    const float* b_left  = (const float*)d_in[4];
    const float* norm_a  = (const float*)d_in[5];
    float* out = (float*)d_out;

    float *p_Xt, *p_Wr, *p_XR, *p_U, *p_V, *p_O;
    cudaGetSymbolAddress((void**)&p_Xt, g_Xt);
    cudaGetSymbolAddress((void**)&p_Wr, g_Wr);
    cudaGetSymbolAddress((void**)&p_XR, g_XR);
    cudaGetSymbolAddress((void**)&p_U,  g_U);
    cudaGetSymbolAddress((void**)&p_V,  g_V);
    cudaGetSymbolAddress((void**)&p_O,  g_O);

    k_transpose_x<<<dim3(2, BATCH), 256>>>(x);
    k_expand_w<<<dim3(2, NIN), 256>>>(w_right);
    k_pack_v<<<dim3(2, NOUT), 256>>>(weight, w_left);

    gemm_kernel<0><<<dim3(8, 4, 8), 256>>>(p_Xt, p_Wr, p_XR);

    k_features<<<dim3(2, BATCH), 256>>>(x, norm_a);

    gemm_kernel<1><<<dim3(8, 4, 8), 256>>>(p_U, p_V, p_O);

    k_interleave<<<(BATCH*NOUT)/256, 256>>>(out, b_left);
}

// round 9
// speedup vs baseline: 1.2263x; 1.2263x over previous
#include <cuda_runtime.h>
#include <cuda_bf16.h>
#include <cstdint>
#include <math.h>

#define BATCH 2048
#define NIN   512
#define NOUT  512
#define NB    8
#define NF    52
#define PLANE (BATCH*NIN)          /* 1048576 */
#define KP1   1536                  /* GEMM0 row length (3*512) */
#define KP2   79872                 /* GEMM1 row length (3*52*512) */
#define BLK2  26624                 /* 52*512 */

// ---------------- static device scratch ----------------
__device__ __align__(256) unsigned short g_A2x[(size_t)NB*BATCH*KP1];  // x split: [i][b][hi|lo|hi]
__device__ __align__(256) unsigned short g_B2w[(size_t)NB*NIN*KP1];    // w_right split: [i][m][hi|hi|lo]
__device__ __align__(256) unsigned short g_U2 [(size_t)BATCH*KP2];     // features split: [b][hi|lo|hi]
__device__ __align__(256) unsigned short g_V2 [(size_t)NOUT*KP2];      // weights split: [m][hi|hi|lo]
__device__ __align__(256) float g_XR[(size_t)NB*PLANE];                // xr blade-major fp32
__device__ __align__(256) float g_O [(size_t)NB*PLANE];                // output planes fp32

// ---------------- PTX helpers (baseline sm_80+ only) ----------------
__device__ __forceinline__ uint32_t smem_u32(const void* p) {
    uint32_t a;
    asm("{ .reg .u64 t; cvta.to.shared.u64 t, %1; cvt.u32.u64 %0, t; }" : "=r"(a) : "l"(p));
    return a;
}
__device__ __forceinline__ void cp16(uint32_t s, const void* g) {
    asm volatile("cp.async.ca.shared.global [%0], [%1], 16;" :: "r"(s), "l"(g) : "memory");
}
#define CP_COMMIT() asm volatile("cp.async.commit_group;" ::: "memory")
#define CP_WAIT1()  asm volatile("cp.async.wait_group 1;" ::: "memory")
#define CP_WAIT0()  asm volatile("cp.async.wait_group 0;" ::: "memory")

__device__ __forceinline__ void ldsm_x4(uint32_t* r, uint32_t a) {
    asm volatile("ldmatrix.sync.aligned.m8n8.x4.shared.b16 {%0,%1,%2,%3}, [%4];"
        : "=r"(r[0]), "=r"(r[1]), "=r"(r[2]), "=r"(r[3]) : "r"(a));
}
__device__ __forceinline__ void ldsm_x2(uint32_t* r, uint32_t a) {
    asm volatile("ldmatrix.sync.aligned.m8n8.x2.shared.b16 {%0,%1}, [%2];"
        : "=r"(r[0]), "=r"(r[1]) : "r"(a));
}
__device__ __forceinline__ void mma16816(float* d, const uint32_t* a, const uint32_t* b) {
    asm volatile(
        "mma.sync.aligned.m16n8k16.row.col.f32.bf16.bf16.f32 "
        "{%0,%1,%2,%3}, {%4,%5,%6,%7}, {%8,%9}, {%0,%1,%2,%3};"
        : "+f"(d[0]), "+f"(d[1]), "+f"(d[2]), "+f"(d[3])
        : "r"(a[0]), "r"(a[1]), "r"(a[2]), "r"(a[3]), "r"(b[0]), "r"(b[1]));
}

// ---------------- bf16 split helper ----------------
__device__ __forceinline__ void bf16split(float v, unsigned short& h, unsigned short& l) {
    __nv_bfloat16 hb = __float2bfloat16_rn(v);
    h = __bfloat16_as_ushort(hb);
    l = __bfloat16_as_ushort(__float2bfloat16_rn(v - __bfloat162float(hb)));
}

// ---------------- conversion kernels ----------------
__global__ void k_conv_x(const float* __restrict__ x) {
    int n = blockIdx.x * 256 + threadIdx.x;
    int b = blockIdx.y;
    const float4* xp = (const float4*)(x + ((size_t)b*NIN + n)*NB);
    float4 x0 = xp[0], x1 = xp[1];
    float X[8] = {x0.x, x0.y, x0.z, x0.w, x1.x, x1.y, x1.z, x1.w};
    #pragma unroll
    for (int i = 0; i < 8; i++) {
        unsigned short h, l; bf16split(X[i], h, l);
        unsigned short* base = g_A2x + (size_t)i*BATCH*KP1 + (size_t)b*KP1 + n;
        base[0] = h; base[512] = l; base[1024] = h;   // A blocks: hi | lo | hi
    }
}

__global__ void k_conv_w(const float* __restrict__ w_right) {
    int n = blockIdx.x * 256 + threadIdx.x;
    int m = blockIdx.y;
    float4 w = *(const float4*)(w_right + ((size_t)m*NIN + n)*4);
    float W[8] = {w.x, w.y, w.y, w.y, w.z, w.z, w.z, w.w};
    #pragma unroll
    for (int i = 0; i < 8; i++) {
        unsigned short h, l; bf16split(W[i], h, l);
        unsigned short* base = g_B2w + (size_t)i*NIN*KP1 + (size_t)m*KP1 + n;
        base[0] = h; base[512] = h; base[1024] = l;   // B blocks: hi | hi | lo
    }
}

__global__ void k_pack_v(const float* __restrict__ weight, const float* __restrict__ w_left) {
    int n = blockIdx.x * 256 + threadIdx.x;
    int m = blockIdx.y;
    const float* wp = weight + ((size_t)m*NIN + n)*20;
    float w[20];
    #pragma unroll
    for (int q = 0; q < 5; q++) {
        float4 v = *(const float4*)(wp + q*4);
        w[q*4+0] = v.x; w[q*4+1] = v.y; w[q*4+2] = v.z; w[q*4+3] = v.w;
    }
    float4 wl4 = *(const float4*)(w_left + ((size_t)m*NIN + n)*4);
    float wl[4] = {wl4.x, wl4.y, wl4.z, wl4.w};
    const int VMAP[NF] = {
        100, 0, 4, 10, 16,
        101, 1, 5, 6, 11, 12, 17,
        101, 1, 5, 6, 11, 12, 17,
        101, 1, 5, 6, 11, 12, 17,
        102, 2, 7, 8, 13, 14, 18,
        102, 2, 7, 8, 13, 14, 18,
        102, 2, 7, 8, 13, 14, 18,
        103, 3, 9, 15, 19
    };
    unsigned short* vb = g_V2 + (size_t)m*KP2 + n;
    #pragma unroll
    for (int f = 0; f < NF; f++) {
        int c = VMAP[f];
        float v = (c >= 100) ? wl[c - 100] : w[c];
        unsigned short h, l; bf16split(v, h, l);
        vb[(size_t)f*512]          = h;               // B blocks: hi | hi | lo
        vb[(size_t)BLK2 + f*512]   = h;
        vb[(size_t)2*BLK2 + f*512] = l;
    }
}

// ---------------- normalize xr + build feature matrix U2 (bf16 split) ----------------
__device__ __forceinline__ void put52(unsigned short* base, int f, float v) {
    unsigned short h, l; bf16split(v, h, l);
    base[(size_t)f*512]          = h;                 // A blocks: hi | lo | hi
    base[(size_t)BLK2 + f*512]   = l;
    base[(size_t)2*BLK2 + f*512] = h;
}

__global__ void k_features(const float* __restrict__ x, const float* __restrict__ norm_a) {
    int n = blockIdx.x * 256 + threadIdx.x;
    int b = blockIdx.y;
    const float4* xp = (const float4*)(x + ((size_t)b*NIN + n)*NB);
    float4 x0 = xp[0], x1 = xp[1];
    float X[8] = {x0.x, x0.y, x0.z, x0.w, x1.x, x1.y, x1.z, x1.w};

    size_t o = (size_t)b*NIN + n;
    float R[8];
    #pragma unroll
    for (int i = 0; i < 8; i++) R[i] = g_XR[(size_t)i*PLANE + o];

    float4 na4 = *(const float4*)(norm_a + (size_t)n*4);
    float na[4] = {na4.x, na4.y, na4.z, na4.w};
    float nrm[4];
    nrm[0] = fabsf(R[0]);
    nrm[1] = sqrtf(R[1]*R[1] + R[2]*R[2] + R[3]*R[3]);
    nrm[2] = sqrtf(R[4]*R[4] + R[5]*R[5] + R[6]*R[6]);
    nrm[3] = fabsf(R[7]);
    float inv[4];
    #pragma unroll
    for (int g = 0; g < 4; g++) {
        float sig = 1.0f / (1.0f + __expf(-na[g]));
        float fac = sig * (nrm[g] - 1.0f) + 1.0f + 1e-6f;
        inv[g] = 1.0f / fac;
    }
    R[0] *= inv[0];
    R[1] *= inv[1]; R[2] *= inv[1]; R[3] *= inv[1];
    R[4] *= inv[2]; R[5] *= inv[2]; R[6] *= inv[2];
    R[7] *= inv[3];

    unsigned short* Up = g_U2 + (size_t)b*KP2 + n;
    put52(Up, 0,  X[0]);
    put52(Up, 1,  X[0]*R[0]);
    put52(Up, 2,  X[1]*R[1] + X[2]*R[2] + X[3]*R[3]);
    put52(Up, 3,  -(X[4]*R[4] + X[5]*R[5] + X[6]*R[6]));
    put52(Up, 4,  -X[7]*R[7]);
    put52(Up, 5,  X[1]);
    put52(Up, 6,  X[0]*R[1]);
    put52(Up, 7,  X[1]*R[0]);
    put52(Up, 8,  -X[2]*R[4] - X[3]*R[5]);
    put52(Up, 9,  X[4]*R[2] + X[5]*R[3]);
    put52(Up, 10, -X[6]*R[7]);
    put52(Up, 11, -X[7]*R[6]);
    put52(Up, 12, X[2]);
    put52(Up, 13, X[0]*R[2]);
    put52(Up, 14, X[2]*R[0]);
    put52(Up, 15, X[1]*R[4] - X[3]*R[6]);
    put52(Up, 16, -X[4]*R[1] + X[6]*R[3]);
    put52(Up, 17, X[5]*R[7]);
    put52(Up, 18, X[7]*R[5]);
    put52(Up, 19, X[3]);
    put52(Up, 20, X[0]*R[3]);
    put52(Up, 21, X[3]*R[0]);
    put52(Up, 22, X[1]*R[5] + X[2]*R[6]);
    put52(Up, 23, -X[5]*R[1] - X[6]*R[2]);
    put52(Up, 24, -X[4]*R[7]);
    put52(Up, 25, -X[7]*R[4]);
    put52(Up, 26, X[4]);
    put52(Up, 27, X[0]*R[4]);
    put52(Up, 28, X[1]*R[2] - X[2]*R[1]);
    put52(Up, 29, X[3]*R[7]);
    put52(Up, 30, X[4]*R[0]);
    put52(Up, 31, -X[5]*R[6] + X[6]*R[5]);
    put52(Up, 32, X[7]*R[3]);
    put52(Up, 33, X[5]);
    put52(Up, 34, X[0]*R[5]);
    put52(Up, 35, X[1]*R[3] - X[3]*R[1]);
    put52(Up, 36, -X[2]*R[7]);
    put52(Up, 37, X[5]*R[0]);
    put52(Up, 38, X[4]*R[6] - X[6]*R[4]);
    put52(Up, 39, -X[7]*R[2]);
    put52(Up, 40, X[6]);
    put52(Up, 41, X[0]*R[6]);
    put52(Up, 42, X[2]*R[3] - X[3]*R[2]);
    put52(Up, 43, X[1]*R[7]);
    put52(Up, 44, X[6]*R[0]);
    put52(Up, 45, -X[4]*R[5] + X[5]*R[4]);
    put52(Up, 46, X[7]*R[1]);
    put52(Up, 47, X[7]);
    put52(Up, 48, X[0]*R[7]);
    put52(Up, 49, X[1]*R[6] - X[2]*R[5] + X[3]*R[4]);
    put52(Up, 50, X[4]*R[3] - X[5]*R[2] + X[6]*R[1]);
    put52(Up, 51, X[7]*R[0]);
}

// ---------------- warp-MMA GEMM: C(2048x512) = A(2048xK3)*B(512xK3)^T per blade ----------------
// CTA tile 128x128, 8 warps (2x4), warp tile 64x32, K-chunk 32 bf16.
// smem rows padded to 80B -> conflict-free ldmatrix/cp.async.
#define ROWB     80
#define AT_BYTES 10240          /* 128 rows * 80B */
#define SB_B0    20480          /* B buffers after A buffers */
#define SM_BYTES 40960

template<int MODE>
__global__ __launch_bounds__(256) void mma_gemm(
    const unsigned short* __restrict__ Abase,
    const unsigned short* __restrict__ Bbase,
    float* __restrict__ Cbase)
{
    extern __shared__ char sm[];
    uint32_t sbase = smem_u32(sm);
    int tid = threadIdx.x;
    int z = blockIdx.z;

    const unsigned short* A;
    const unsigned short* B;
    float* C;
    size_t lda, ldb;
    int ncb, blkstride, koff;
    if (MODE == 0) {
        A = Abase + (size_t)z*BATCH*KP1; lda = KP1;
        B = Bbase + (size_t)z*NIN*KP1;   ldb = KP1;
        C = Cbase + (size_t)z*PLANE;
        ncb = 16; blkstride = 512; koff = 0;      // 3 contiguous 512-blocks
    } else {
        int F   = (z == 0 || z == 7) ? 5 : 7;
        int off = (z == 0) ? 0 : (5 + 7*(z-1));
        A = Abase; lda = KP2;
        B = Bbase; ldb = KP2;
        C = Cbase + (size_t)z*PLANE;
        ncb = F*16; blkstride = BLK2; koff = off*512;
    }
    int nc = ncb * 3;
    int mB = blockIdx.x * 128;
    int nB = blockIdx.y * 128;

    // ---- cp.async staging: thread -> (row, 16B-chunk) ----
    int grow = tid & 127;                    // row 0..127 (same for A and B tiles)
    const unsigned short* Arow = A + (size_t)(mB + grow)*lda;
    const unsigned short* Brow = B + (size_t)(nB + grow)*ldb;
    uint32_t sArow = sbase + (uint32_t)grow*ROWB;
    uint32_t sBrow = sbase + SB_B0 + (uint32_t)grow*ROWB;
    int c4a = tid >> 7;                      // 0..1; +2*q gives 0..3

#define ISSUE(bufi, k3) do {                                               \
    _Pragma("unroll")                                                      \
    for (int q = 0; q < 2; q++) {                                          \
        int c4 = c4a + 2*q;                                                \
        cp16(sArow + (bufi)*AT_BYTES + c4*16, Arow + (k3) + c4*8);         \
        cp16(sBrow + (bufi)*AT_BYTES + c4*16, Brow + (k3) + c4*8);         \
    }                                                                      \
} while (0)

    // ---- warp/lane fragment addressing ----
    int wid = tid >> 5, lane = tid & 31;
    int wm = wid >> 2, wn = wid & 3;         // warp tile = (wm*64, wn*32)
    int aRow = lane & 15, aSel = lane >> 4;  // canonical A ldmatrix.x4 mapping
    int bRow = lane & 7,  bSel = (lane >> 3) & 1;
    uint32_t aAddr = sbase + (uint32_t)(wm*64 + aRow)*ROWB + aSel*16;
    uint32_t bAddr = sbase + SB_B0 + (uint32_t)(wn*32 + bRow)*ROWB + bSel*16;

    float acc[4][4][4];
    #pragma unroll
    for (int i = 0; i < 4; i++)
        #pragma unroll
        for (int j = 0; j < 4; j++)
            #pragma unroll
            for (int q = 0; q < 4; q++) acc[i][j][q] = 0.0f;

    ISSUE(0, koff);
    CP_COMMIT();

    int blk = 0, wi = 0;
    for (int c = 0; c < nc; c++) {
        if (++wi == ncb) { wi = 0; ++blk; }  // indices now describe chunk c+1
        if (c + 1 < nc) {
            ISSUE((c + 1) & 1, blk*blkstride + koff + wi*32);
            CP_COMMIT();
            CP_WAIT1();
        } else {
            CP_WAIT0();
        }
        __syncthreads();
        uint32_t bo = (uint32_t)(c & 1) * AT_BYTES;
        #pragma unroll
        for (int ks = 0; ks < 2; ks++) {
            uint32_t af[4][4], bf[4][2];
            #pragma unroll
            for (int i = 0; i < 4; i++) ldsm_x4(af[i], aAddr + bo + i*(16*ROWB) + ks*32);
            #pragma unroll
            for (int j = 0; j < 4; j++) ldsm_x2(bf[j], bAddr + bo + j*(8*ROWB) + ks*32);
            #pragma unroll
            for (int i = 0; i < 4; i++)
                #pragma unroll
                for (int j = 0; j < 4; j++)
                    mma16816(acc[i][j], af[i], bf[j]);
        }
        __syncthreads();
    }

    // ---- epilogue: c0,c1 -> (row lane/4, col 2*(lane%3..)), c2,c3 -> row+8 ----
    int r0 = mB + wm*64 + (lane >> 2);
    int c0 = nB + wn*32 + 2*(lane & 3);
    #pragma unroll
    for (int i = 0; i < 4; i++) {
        #pragma unroll
        for (int j = 0; j < 4; j++) {
            float* p0 = C + (size_t)(r0 + 16*i)*NOUT + c0 + 8*j;
            float* p1 = p0 + 8*NOUT;
            *(float2*)p0 = make_float2(acc[i][j][0], acc[i][j][1]);
            *(float2*)p1 = make_float2(acc[i][j][2], acc[i][j][3]);
        }
    }
#undef ISSUE
}

// ---------------- final interleave + bias + 1/sqrt(2) ----------------
__global__ void k_interleave(float* __restrict__ out, const float* __restrict__ b_left) {
    size_t idx = (size_t)blockIdx.x * 256 + threadIdx.x;  // = b*512 + m
    const float r = 0.7071067811865476f;
    int m = (int)(idx & 511);
    float4 o0, o1;
    o0.x = (g_O[(size_t)0*PLANE + idx] + b_left[m]) * r;
    o0.y =  g_O[(size_t)1*PLANE + idx] * r;
    o0.z =  g_O[(size_t)2*PLANE + idx] * r;
    o0.w =  g_O[(size_t)3*PLANE + idx] * r;
    o1.x =  g_O[(size_t)4*PLANE + idx] * r;
    o1.y =  g_O[(size_t)5*PLANE + idx] * r;
    o1.z =  g_O[(size_t)6*PLANE + idx] * r;
    o1.w =  g_O[(size_t)7*PLANE + idx] * r;
    ((float4*)out)[idx*2 + 0] = o0;
    ((float4*)out)[idx*2 + 1] = o1;
}

// ---------------- launch ----------------
extern "C" void kernel_launch(void* const* d_in, const int* in_sizes, int n_in,
                              void* d_out, int out_size) {
    const float* x       = (const float*)d_in[0];
    const float* weight  = (const float*)d_in[1];
    const float* w_right = (const float*)d_in[2];
    const float* w_left  = (const float*)d_in[3];
    const float* b_left  = (const float*)d_in[4];
    const float* norm_a  = (const float*)d_in[5];
    float* out = (float*)d_out;

    unsigned short *p_A2x, *p_B2w, *p_U2, *p_V2;
    float *p_XR, *p_O;
    cudaGetSymbolAddress((void**)&p_A2x, g_A2x);
    cudaGetSymbolAddress((void**)&p_B2w, g_B2w);
    cudaGetSymbolAddress((void**)&p_U2,  g_U2);
    cudaGetSymbolAddress((void**)&p_V2,  g_V2);
    cudaGetSymbolAddress((void**)&p_XR,  g_XR);
    cudaGetSymbolAddress((void**)&p_O,   g_O);

    k_conv_x<<<dim3(2, BATCH), 256>>>(x);
    k_conv_w<<<dim3(2, NIN), 256>>>(w_right);
    k_pack_v<<<dim3(2, NOUT), 256>>>(weight, w_left);

    mma_gemm<0><<<dim3(16, 4, 8), 256, SM_BYTES>>>(p_A2x, p_B2w, p_XR);

    k_features<<<dim3(2, BATCH), 256>>>(x, norm_a);

    mma_gemm<1><<<dim3(16, 4, 8), 256, SM_BYTES>>>(p_U2, p_V2, p_O);

    k_interleave<<<(BATCH*NOUT)/256, 256>>>(out, b_left);
}

// round 10
// speedup vs baseline: 1.5468x; 1.2614x over previous
#include <cuda_runtime.h>
#include <cuda_bf16.h>
#include <cstdint>
#include <math.h>

#define BATCH 2048
#define NIN   512
#define NOUT  512
#define NB    8
#define NF    52
#define PLANE (BATCH*NIN)          /* 1048576 */
#define KP1   1024                  /* GEMM0 row: hi(512)|lo(512) */
#define BLK1  512
#define KP2   53248                 /* GEMM1 row: hi(26624)|lo(26624) */
#define BLK2  26624                 /* 52*512 */

// ---------------- static device scratch ----------------
__device__ __align__(256) unsigned short g_A2x[(size_t)NB*BATCH*KP1];  // x split: [i][b][hi|lo]
__device__ __align__(256) unsigned short g_B2w[(size_t)NB*NIN*KP1];    // w_right split: [i][m][hi|lo]
__device__ __align__(256) unsigned short g_U2 [(size_t)BATCH*KP2];     // features split: [b][hi|lo]
__device__ __align__(256) unsigned short g_V2 [(size_t)NOUT*KP2];      // weights split: [m][hi|lo]
__device__ __align__(256) float g_XR[(size_t)NB*PLANE];                // xr blade-major fp32
__device__ __align__(256) float g_O [(size_t)NB*PLANE];                // output planes fp32

// ---------------- PTX helpers (baseline sm_80+ only) ----------------
__device__ __forceinline__ uint32_t smem_u32(const void* p) {
    uint32_t a;
    asm("{ .reg .u64 t; cvta.to.shared.u64 t, %1; cvt.u32.u64 %0, t; }" : "=r"(a) : "l"(p));
    return a;
}
__device__ __forceinline__ void cp16(uint32_t s, const void* g) {
    asm volatile("cp.async.ca.shared.global [%0], [%1], 16;" :: "r"(s), "l"(g) : "memory");
}
#define CP_COMMIT() asm volatile("cp.async.commit_group;" ::: "memory")
#define CP_WAIT1()  asm volatile("cp.async.wait_group 1;" ::: "memory")
#define CP_WAIT0()  asm volatile("cp.async.wait_group 0;" ::: "memory")

__device__ __forceinline__ void ldsm_x4(uint32_t* r, uint32_t a) {
    asm volatile("ldmatrix.sync.aligned.m8n8.x4.shared.b16 {%0,%1,%2,%3}, [%4];"
        : "=r"(r[0]), "=r"(r[1]), "=r"(r[2]), "=r"(r[3]) : "r"(a));
}
__device__ __forceinline__ void ldsm_x2(uint32_t* r, uint32_t a) {
    asm volatile("ldmatrix.sync.aligned.m8n8.x2.shared.b16 {%0,%1}, [%2];"
        : "=r"(r[0]), "=r"(r[1]) : "r"(a));
}
__device__ __forceinline__ void mma16816(float* d, const uint32_t* a, const uint32_t* b) {
    asm volatile(
        "mma.sync.aligned.m16n8k16.row.col.f32.bf16.bf16.f32 "
        "{%0,%1,%2,%3}, {%4,%5,%6,%7}, {%8,%9}, {%0,%1,%2,%3};"
        : "+f"(d[0]), "+f"(d[1]), "+f"(d[2]), "+f"(d[3])
        : "r"(a[0]), "r"(a[1]), "r"(a[2]), "r"(a[3]), "r"(b[0]), "r"(b[1]));
}

// ---------------- bf16 split helper ----------------
__device__ __forceinline__ void bf16split(float v, unsigned short& h, unsigned short& l) {
    __nv_bfloat16 hb = __float2bfloat16_rn(v);
    h = __bfloat16_as_ushort(hb);
    l = __bfloat16_as_ushort(__float2bfloat16_rn(v - __bfloat162float(hb)));
}

// ---------------- conversion kernels ----------------
__global__ void k_conv_x(const float* __restrict__ x) {
    int n = blockIdx.x * 256 + threadIdx.x;
    int b = blockIdx.y;
    const float4* xp = (const float4*)(x + ((size_t)b*NIN + n)*NB);
    float4 x0 = xp[0], x1 = xp[1];
    float X[8] = {x0.x, x0.y, x0.z, x0.w, x1.x, x1.y, x1.z, x1.w};
    #pragma unroll
    for (int i = 0; i < 8; i++) {
        unsigned short h, l; bf16split(X[i], h, l);
        unsigned short* base = g_A2x + (size_t)i*BATCH*KP1 + (size_t)b*KP1 + n;
        base[0] = h; base[BLK1] = l;
    }
}

__global__ void k_conv_w(const float* __restrict__ w_right) {
    int n = blockIdx.x * 256 + threadIdx.x;
    int m = blockIdx.y;
    float4 w = *(const float4*)(w_right + ((size_t)m*NIN + n)*4);
    float W[8] = {w.x, w.y, w.y, w.y, w.z, w.z, w.z, w.w};
    #pragma unroll
    for (int i = 0; i < 8; i++) {
        unsigned short h, l; bf16split(W[i], h, l);
        unsigned short* base = g_B2w + (size_t)i*NIN*KP1 + (size_t)m*KP1 + n;
        base[0] = h; base[BLK1] = l;
    }
}

__global__ void k_pack_v(const float* __restrict__ weight, const float* __restrict__ w_left) {
    int n = blockIdx.x * 256 + threadIdx.x;
    int m = blockIdx.y;
    const float* wp = weight + ((size_t)m*NIN + n)*20;
    float w[20];
    #pragma unroll
    for (int q = 0; q < 5; q++) {
        float4 v = *(const float4*)(wp + q*4);
        w[q*4+0] = v.x; w[q*4+1] = v.y; w[q*4+2] = v.z; w[q*4+3] = v.w;
    }
    float4 wl4 = *(const float4*)(w_left + ((size_t)m*NIN + n)*4);
    float wl[4] = {wl4.x, wl4.y, wl4.z, wl4.w};
    const int VMAP[NF] = {
        100, 0, 4, 10, 16,
        101, 1, 5, 6, 11, 12, 17,
        101, 1, 5, 6, 11, 12, 17,
        101, 1, 5, 6, 11, 12, 17,
        102, 2, 7, 8, 13, 14, 18,
        102, 2, 7, 8, 13, 14, 18,
        102, 2, 7, 8, 13, 14, 18,
        103, 3, 9, 15, 19
    };
    unsigned short* vb = g_V2 + (size_t)m*KP2 + n;
    #pragma unroll
    for (int f = 0; f < NF; f++) {
        int c = VMAP[f];
        float v = (c >= 100) ? wl[c - 100] : w[c];
        unsigned short h, l; bf16split(v, h, l);
        vb[(size_t)f*512]        = h;
        vb[(size_t)BLK2 + f*512] = l;
    }
}

// ---------------- normalize xr + build feature matrix U2 (bf16 split) ----------------
__device__ __forceinline__ void put52(unsigned short* base, int f, float v) {
    unsigned short h, l; bf16split(v, h, l);
    base[(size_t)f*512]        = h;
    base[(size_t)BLK2 + f*512] = l;
}

__global__ void k_features(const float* __restrict__ x, const float* __restrict__ norm_a) {
    int n = blockIdx.x * 256 + threadIdx.x;
    int b = blockIdx.y;
    const float4* xp = (const float4*)(x + ((size_t)b*NIN + n)*NB);
    float4 x0 = xp[0], x1 = xp[1];
    float X[8] = {x0.x, x0.y, x0.z, x0.w, x1.x, x1.y, x1.z, x1.w};

    size_t o = (size_t)b*NIN + n;
    float R[8];
    #pragma unroll
    for (int i = 0; i < 8; i++) R[i] = g_XR[(size_t)i*PLANE + o];

    float4 na4 = *(const float4*)(norm_a + (size_t)n*4);
    float na[4] = {na4.x, na4.y, na4.z, na4.w};
    float nrm[4];
    nrm[0] = fabsf(R[0]);
    nrm[1] = sqrtf(R[1]*R[1] + R[2]*R[2] + R[3]*R[3]);
    nrm[2] = sqrtf(R[4]*R[4] + R[5]*R[5] + R[6]*R[6]);
    nrm[3] = fabsf(R[7]);
    float inv[4];
    #pragma unroll
    for (int g = 0; g < 4; g++) {
        float sig = 1.0f / (1.0f + __expf(-na[g]));
        float fac = sig * (nrm[g] - 1.0f) + 1.0f + 1e-6f;
        inv[g] = 1.0f / fac;
    }
    R[0] *= inv[0];
    R[1] *= inv[1]; R[2] *= inv[1]; R[3] *= inv[1];
    R[4] *= inv[2]; R[5] *= inv[2]; R[6] *= inv[2];
    R[7] *= inv[3];

    unsigned short* Up = g_U2 + (size_t)b*KP2 + n;
    put52(Up, 0,  X[0]);
    put52(Up, 1,  X[0]*R[0]);
    put52(Up, 2,  X[1]*R[1] + X[2]*R[2] + X[3]*R[3]);
    put52(Up, 3,  -(X[4]*R[4] + X[5]*R[5] + X[6]*R[6]));
    put52(Up, 4,  -X[7]*R[7]);
    put52(Up, 5,  X[1]);
    put52(Up, 6,  X[0]*R[1]);
    put52(Up, 7,  X[1]*R[0]);
    put52(Up, 8,  -X[2]*R[4] - X[3]*R[5]);
    put52(Up, 9,  X[4]*R[2] + X[5]*R[3]);
    put52(Up, 10, -X[6]*R[7]);
    put52(Up, 11, -X[7]*R[6]);
    put52(Up, 12, X[2]);
    put52(Up, 13, X[0]*R[2]);
    put52(Up, 14, X[2]*R[0]);
    put52(Up, 15, X[1]*R[4] - X[3]*R[6]);
    put52(Up, 16, -X[4]*R[1] + X[6]*R[3]);
    put52(Up, 17, X[5]*R[7]);
    put52(Up, 18, X[7]*R[5]);
    put52(Up, 19, X[3]);
    put52(Up, 20, X[0]*R[3]);
    put52(Up, 21, X[3]*R[0]);
    put52(Up, 22, X[1]*R[5] + X[2]*R[6]);
    put52(Up, 23, -X[5]*R[1] - X[6]*R[2]);
    put52(Up, 24, -X[4]*R[7]);
    put52(Up, 25, -X[7]*R[4]);
    put52(Up, 26, X[4]);
    put52(Up, 27, X[0]*R[4]);
    put52(Up, 28, X[1]*R[2] - X[2]*R[1]);
    put52(Up, 29, X[3]*R[7]);
    put52(Up, 30, X[4]*R[0]);
    put52(Up, 31, -X[5]*R[6] + X[6]*R[5]);
    put52(Up, 32, X[7]*R[3]);
    put52(Up, 33, X[5]);
    put52(Up, 34, X[0]*R[5]);
    put52(Up, 35, X[1]*R[3] - X[3]*R[1]);
    put52(Up, 36, -X[2]*R[7]);
    put52(Up, 37, X[5]*R[0]);
    put52(Up, 38, X[4]*R[6] - X[6]*R[4]);
    put52(Up, 39, -X[7]*R[2]);
    put52(Up, 40, X[6]);
    put52(Up, 41, X[0]*R[6]);
    put52(Up, 42, X[2]*R[3] - X[3]*R[2]);
    put52(Up, 43, X[1]*R[7]);
    put52(Up, 44, X[6]*R[0]);
    put52(Up, 45, -X[4]*R[5] + X[5]*R[4]);
    put52(Up, 46, X[7]*R[1]);
    put52(Up, 47, X[7]);
    put52(Up, 48, X[0]*R[7]);
    put52(Up, 49, X[1]*R[6] - X[2]*R[5] + X[3]*R[4]);
    put52(Up, 50, X[4]*R[3] - X[5]*R[2] + X[6]*R[1]);
    put52(Up, 51, X[7]*R[0]);
}

// ---------------- warp-MMA GEMM with in-register split-product ----------------
// CTA tile 128x128, 4 warps (2x2), warp tile 64x64, K-chunk 32 bf16.
// Per chunk: load Ahi, Alo, Bhi, Blo tiles; acc += Ahi*Bhi + Alo*Bhi + Ahi*Blo.
#define ROWB     80
#define TILE_B   10240          /* 128 rows * 80B */
#define OFF_ALO  10240
#define OFF_BHI  20480
#define OFF_BLO  30720
#define BUF_B    40960
#define SM_BYTES 81920

template<int MODE>
__global__ __launch_bounds__(128) void mma_gemm(
    const unsigned short* __restrict__ Abase,
    const unsigned short* __restrict__ Bbase,
    float* __restrict__ Cbase)
{
    extern __shared__ char sm[];
    uint32_t sbase = smem_u32(sm);
    int tid = threadIdx.x;
    int z = blockIdx.z;

    const unsigned short* A;
    const unsigned short* B;
    float* C;
    size_t lda, ldb, blkA, blkB;
    int nc, koff;
    if (MODE == 0) {
        A = Abase + (size_t)z*BATCH*KP1; lda = KP1; blkA = BLK1;
        B = Bbase + (size_t)z*NIN*KP1;   ldb = KP1; blkB = BLK1;
        C = Cbase + (size_t)z*PLANE;
        nc = 16; koff = 0;
    } else {
        int F   = (z == 0 || z == 7) ? 5 : 7;
        int off = (z == 0) ? 0 : (5 + 7*(z-1));
        A = Abase; lda = KP2; blkA = BLK2;
        B = Bbase; ldb = KP2; blkB = BLK2;
        C = Cbase + (size_t)z*PLANE;
        nc = F*16; koff = off*512;
    }
    int mB = blockIdx.x * 128;
    int nB = blockIdx.y * 128;

    // ---- cp.async staging: each thread owns one row of each of the 4 tiles ----
    const unsigned short* ArowH = A + (size_t)(mB + tid)*lda;
    const unsigned short* ArowL = ArowH + blkA;
    const unsigned short* BrowH = B + (size_t)(nB + tid)*ldb;
    const unsigned short* BrowL = BrowH + blkB;
    uint32_t sRow = sbase + (uint32_t)tid*ROWB;

#define ISSUE(bufi, k3) do {                                               \
    _Pragma("unroll")                                                      \
    for (int c4 = 0; c4 < 4; c4++) {                                       \
        uint32_t d = sRow + (bufi)*BUF_B + c4*16;                          \
        cp16(d,            ArowH + (k3) + c4*8);                           \
        cp16(d + OFF_ALO,  ArowL + (k3) + c4*8);                           \
        cp16(d + OFF_BHI,  BrowH + (k3) + c4*8);                           \
        cp16(d + OFF_BLO,  BrowL + (k3) + c4*8);                           \
    }                                                                      \
} while (0)

    // ---- warp/lane fragment addressing ----
    int wid = tid >> 5, lane = tid & 31;
    int wm = wid >> 1, wn = wid & 1;         // warp tile = (wm*64, wn*64)
    int aRow = lane & 15, aSel = lane >> 4;
    int bRow = lane & 7,  bSel = (lane >> 3) & 1;
    uint32_t aAddr = sbase + (uint32_t)(wm*64 + aRow)*ROWB + aSel*16;
    uint32_t bAddr = sbase + OFF_BHI + (uint32_t)(wn*64 + bRow)*ROWB + bSel*16;

    float acc[4][8][4];
    #pragma unroll
    for (int i = 0; i < 4; i++)
        #pragma unroll
        for (int j = 0; j < 8; j++)
            #pragma unroll
            for (int q = 0; q < 4; q++) acc[i][j][q] = 0.0f;

    ISSUE(0, koff);
    CP_COMMIT();

    for (int c = 0; c < nc; c++) {
        if (c + 1 < nc) {
            ISSUE((c + 1) & 1, koff + (c + 1)*32);
            CP_COMMIT();
            CP_WAIT1();
        } else {
            CP_WAIT0();
        }
        __syncthreads();
        uint32_t bo = (uint32_t)(c & 1) * BUF_B;
        #pragma unroll
        for (int ks = 0; ks < 2; ks++) {
            uint32_t afh[4][4], afl[4][4];
            #pragma unroll
            for (int i = 0; i < 4; i++) ldsm_x4(afh[i], aAddr + bo + i*(16*ROWB) + ks*32);
            #pragma unroll
            for (int i = 0; i < 4; i++) ldsm_x4(afl[i], aAddr + bo + OFF_ALO + i*(16*ROWB) + ks*32);
            #pragma unroll
            for (int jb = 0; jb < 2; jb++) {
                uint32_t bfh[4][2], bfl[4][2];
                #pragma unroll
                for (int j = 0; j < 4; j++)
                    ldsm_x2(bfh[j], bAddr + bo + (jb*32 + j*8)*ROWB + ks*32);
                #pragma unroll
                for (int j = 0; j < 4; j++)
                    ldsm_x2(bfl[j], bAddr + bo + OFF_ALO + (jb*32 + j*8)*ROWB + ks*32);
                #pragma unroll
                for (int i = 0; i < 4; i++)
                    #pragma unroll
                    for (int j = 0; j < 4; j++) {
                        mma16816(acc[i][jb*4+j], afh[i], bfh[j]);
                        mma16816(acc[i][jb*4+j], afl[i], bfh[j]);
                        mma16816(acc[i][jb*4+j], afh[i], bfl[j]);
                    }
            }
        }
        __syncthreads();
    }

    // ---- epilogue ----
    int r0 = mB + wm*64 + (lane >> 2);
    int c0 = nB + wn*64 + 2*(lane & 3);
    #pragma unroll
    for (int i = 0; i < 4; i++) {
        #pragma unroll
        for (int j = 0; j < 8; j++) {
            float* p0 = C + (size_t)(r0 + 16*i)*NOUT + c0 + 8*j;
            float* p1 = p0 + 8*NOUT;
            *(float2*)p0 = make_float2(acc[i][j][0], acc[i][j][1]);
            *(float2*)p1 = make_float2(acc[i][j][2], acc[i][j][3]);
        }
    }
#undef ISSUE
}

// ---------------- final interleave + bias + 1/sqrt(2) ----------------
__global__ void k_interleave(float* __restrict__ out, const float* __restrict__ b_left) {
    size_t idx = (size_t)blockIdx.x * 256 + threadIdx.x;  // = b*512 + m
    const float r = 0.7071067811865476f;
    int m = (int)(idx & 511);
    float4 o0, o1;
    o0.x = (g_O[(size_t)0*PLANE + idx] + b_left[m]) * r;
    o0.y =  g_O[(size_t)1*PLANE + idx] * r;
    o0.z =  g_O[(size_t)2*PLANE + idx] * r;
    o0.w =  g_O[(size_t)3*PLANE + idx] * r;
    o1.x =  g_O[(size_t)4*PLANE + idx] * r;
    o1.y =  g_O[(size_t)5*PLANE + idx] * r;
    o1.z =  g_O[(size_t)6*PLANE + idx] * r;
    o1.w =  g_O[(size_t)7*PLANE + idx] * r;
    ((float4*)out)[idx*2 + 0] = o0;
    ((float4*)out)[idx*2 + 1] = o1;
}

// ---------------- launch ----------------
extern "C" void kernel_launch(void* const* d_in, const int* in_sizes, int n_in,
                              void* d_out, int out_size) {
    const float* x       = (const float*)d_in[0];
    const float* weight  = (const float*)d_in[1];
    const float* w_right = (const float*)d_in[2];
    const float* w_left  = (const float*)d_in[3];
    const float* b_left  = (const float*)d_in[4];
    const float* norm_a  = (const float*)d_in[5];
    float* out = (float*)d_out;

    unsigned short *p_A2x, *p_B2w, *p_U2, *p_V2;
    float *p_XR, *p_O;
    cudaGetSymbolAddress((void**)&p_A2x, g_A2x);
    cudaGetSymbolAddress((void**)&p_B2w, g_B2w);
    cudaGetSymbolAddress((void**)&p_U2,  g_U2);
    cudaGetSymbolAddress((void**)&p_V2,  g_V2);
    cudaGetSymbolAddress((void**)&p_XR,  g_XR);
    cudaGetSymbolAddress((void**)&p_O,   g_O);

    cudaFuncSetAttribute(mma_gemm<0>, cudaFuncAttributeMaxDynamicSharedMemorySize, SM_BYTES);
    cudaFuncSetAttribute(mma_gemm<1>, cudaFuncAttributeMaxDynamicSharedMemorySize, SM_BYTES);

    k_conv_x<<<dim3(2, BATCH), 256>>>(x);
    k_conv_w<<<dim3(2, NIN), 256>>>(w_right);
    k_pack_v<<<dim3(2, NOUT), 256>>>(weight, w_left);

    mma_gemm<0><<<dim3(16, 4, 8), 128, SM_BYTES>>>(p_A2x, p_B2w, p_XR);

    k_features<<<dim3(2, BATCH), 256>>>(x, norm_a);

    mma_gemm<1><<<dim3(16, 4, 8), 128, SM_BYTES>>>(p_U2, p_V2, p_O);

    k_interleave<<<(BATCH*NOUT)/256, 256>>>(out, b_left);
}